// round 14
// baseline (speedup 1.0000x reference)
#include <cuda_runtime.h>

// Fixed shapes: B=4, C=256, H=W=160, CPS=16 -> nv=nh=10, N=100, NPAT=400/branch
#define HH   160
#define WW   160
#define CC   256
#define NPAT 400
#define ENC  128

__device__ float g_conv_out[2 * NPAT * 256];   // [branch][patch][pix]
__device__ float g_emb[2 * NPAT * ENC];        // only e2 half (rows 400..799) used
__device__ unsigned g_cnt0;                    // branch-0 launch-index tickets
__device__ unsigned g_cnt1;                    // branch-1 completion arrivals

// ---------------------------------------------------------------------------
// Kernel A: channel-reduce conv + bias + relu. K split 4 ways (measured best:
// 34.4us @ 78.5% DRAM). 800 blocks x 256 threads; block = 64 f4 outputs.
// ---------------------------------------------------------------------------
__global__ void __launch_bounds__(256) conv_kernel(
    const float* __restrict__ f1, const float* __restrict__ f2,
    const float* __restrict__ w_img, const float* __restrict__ b_img,
    const float* __restrict__ w_dep, const float* __restrict__ b_dep)
{
    __shared__ float  ws[256];
    __shared__ float4 part[4][64];
    __shared__ float  bias_s;

    const int t      = threadIdx.x;
    const int branch = blockIdx.x / 400;
    const int item0  = (blockIdx.x % 400) * 64;

    const float* wsrc = branch ? w_dep : w_img;
    ws[t] = wsrc[t];
    if (t == 0) bias_s = branch ? b_dep[0] : b_img[0];
    __syncthreads();

    const int kg = t >> 6;        // channel group 0..3
    const int ol = t & 63;
    const int r  = item0 + ol;    // 0..25599 (float4 items per branch)
    const int b  = r / 6400;      // 160*40 float4 per image
    const int r2 = r % 6400;
    const int h  = r2 / 40;
    const int w0 = (r2 % 40) * 4;

    const float* feat  = branch ? f2 : f1;
    const float4* base = (const float4*)(feat + (size_t)b * CC * HH * WW + h * WW + w0)
                         + (size_t)kg * 64 * 6400;   // channel stride = 6400 f4

    float4 acc = make_float4(0.f, 0.f, 0.f, 0.f);
    #pragma unroll 16
    for (int c = 0; c < 64; c++) {
        float4 v = base[c * 6400];
        float wc = ws[kg * 64 + c];
        acc.x = fmaf(v.x, wc, acc.x);
        acc.y = fmaf(v.y, wc, acc.y);
        acc.z = fmaf(v.z, wc, acc.z);
        acc.w = fmaf(v.w, wc, acc.w);
    }
    part[kg][ol] = acc;
    __syncthreads();

    if (t < 64) {
        float4 p0 = part[0][t], p1 = part[1][t], p2 = part[2][t], p3 = part[3][t];
        const float bb = bias_s;
        float4 o4;
        o4.x = fmaxf(p0.x + p1.x + p2.x + p3.x + bb, 0.f);
        o4.y = fmaxf(p0.y + p1.y + p2.y + p3.y + bb, 0.f);
        o4.z = fmaxf(p0.z + p1.z + p2.z + p3.z + bb, 0.f);
        o4.w = fmaxf(p0.w + p1.w + p2.w + p3.w + bb, 0.f);

        const int rr  = item0 + t;
        const int bb2 = rr / 6400;
        const int rr2 = rr % 6400;
        const int hh  = rr2 / 40;
        const int ww0 = (rr2 % 40) * 4;
        const int p   = bb2 * 100 + (hh >> 4) * 10 + (ww0 >> 4);
        const int pix = (hh & 15) * 16 + (ww0 & 15);
        *(float4*)&g_conv_out[(size_t)branch * NPAT * 256 + p * 256 + pix] = o4;
    }
}

// ---------------------------------------------------------------------------
// Kernel B: fused MLP + LN + half-barrier + logits. 100 blocks x 512 threads.
// smem ~200KB -> 1 block/SM -> all 100 blocks co-resident (barrier safe).
// Branch-1 blocks (50..99): MLP -> LN -> write e2 to g_emb -> fence -> arrive
//   on g_cnt1 -> exit.
// Branch-0 blocks (0..49): MLP -> LN in-place into ys (e1 NEVER leaves smem)
//   -> wait g_cnt1 -> logits for THEIR 8 n-rows (two 4-row batch-uniform
//   groups; each e2 LDG.128 feeds 16 FMA over 4 rows).
// smem floats: ws 32768 | asT 3072 | h1T 3072 | red 10240 | ys 1056
// ---------------------------------------------------------------------------
#define MLP_SMEM_FLOATS (32768 + 3072 + 3072 + 10240 + 1056)
#define MLP_SMEM_BYTES  (MLP_SMEM_FLOATS * 4)

__global__ void __launch_bounds__(512) tail_kernel(
    const float* __restrict__ w1_img, const float* __restrict__ w2_img,
    const float* __restrict__ g_img,  const float* __restrict__ be_img,
    const float* __restrict__ w1_dep, const float* __restrict__ w2_dep,
    const float* __restrict__ g_dep,  const float* __restrict__ be_dep,
    const float* __restrict__ logit_scale, float* __restrict__ out)
{
    extern __shared__ float sm[];
    float* ws_ = sm;                        // [256][128] swizzled weight tile
    float* asT = sm + 32768;                // [256][12]  x transposed
    float* h1T = sm + 32768 + 3072;         // [256][12]  h1 transposed
    float* red = sm + 32768 + 6144;         // [512 threads][20]
    float* ys  = sm + 32768 + 6144 + 10240; // [8][132]  y, then normalized e1

    const int t      = threadIdx.x;
    const int branch = blockIdx.x / 50;
    const int p0     = blockIdx.x * 8;      // global patch base (0..792)

    const float* w1 = branch ? w1_dep : w1_img;
    const float* w2 = branch ? w2_dep : w2_img;

    // --- load asT[k][p] from g_conv_out: one f4 per thread ---
    {
        const int p  = t >> 6;        // 0..7
        const int k4 = t & 63;
        float4 v = *(const float4*)&g_conv_out[(size_t)(p0 + p) * 256 + k4 * 4];
        asT[(k4 * 4 + 0) * 12 + p] = v.x;
        asT[(k4 * 4 + 1) * 12 + p] = v.y;
        asT[(k4 * 4 + 2) * 12 + p] = v.z;
        asT[(k4 * 4 + 3) * 12 + p] = v.w;
    }

    const int ox = t & 31;         // 4 outputs  ox*4..ox*4+3
    const int pg = (t >> 5) & 1;   // patches pg*4..pg*4+3
    const int kq = t >> 6;         // 32-k chunk (0..7)

    #pragma unroll 1
    for (int phase = 0; phase < 3; phase++) {
        const float* wsrc = (phase == 0) ? w1 : (phase == 1 ? w1 + 128 * 256 : w2);

        // --- stream 128x256 weight tile, 4x4 reg transpose, swizzled store ---
        {
            const int k4 = t & 63;
            const int og = t >> 6;   // 0..7
            #pragma unroll
            for (int j = 0; j < 4; j++) {
                const int ob = og * 16 + j * 4;
                const int o4 = og * 4 + j;     // 0..31
                float4 v0 = *(const float4*)&wsrc[(size_t)(ob + 0) * 256 + k4 * 4];
                float4 v1 = *(const float4*)&wsrc[(size_t)(ob + 1) * 256 + k4 * 4];
                float4 v2 = *(const float4*)&wsrc[(size_t)(ob + 2) * 256 + k4 * 4];
                float4 v3 = *(const float4*)&wsrc[(size_t)(ob + 3) * 256 + k4 * 4];
                float4 t0 = make_float4(v0.x, v1.x, v2.x, v3.x);
                float4 t1 = make_float4(v0.y, v1.y, v2.y, v3.y);
                float4 t2 = make_float4(v0.z, v1.z, v2.z, v3.z);
                float4 t3 = make_float4(v0.w, v1.w, v2.w, v3.w);
                const int kb = k4 * 4;
                *(float4*)&ws_[(kb + 0) * 128 + ((o4 ^ ((kb + 0) & 31)) << 2)] = t0;
                *(float4*)&ws_[(kb + 1) * 128 + ((o4 ^ ((kb + 1) & 31)) << 2)] = t1;
                *(float4*)&ws_[(kb + 2) * 128 + ((o4 ^ ((kb + 2) & 31)) << 2)] = t2;
                *(float4*)&ws_[(kb + 3) * 128 + ((o4 ^ ((kb + 3) & 31)) << 2)] = t3;
            }
        }
        __syncthreads();

        // --- compute: 4 outs x 4 patches over this thread's 32-k chunk ---
        const float* xsrc = (phase < 2) ? asT : h1T;
        float a00 = 0.f, a01 = 0.f, a02 = 0.f, a03 = 0.f;
        float a10 = 0.f, a11 = 0.f, a12 = 0.f, a13 = 0.f;
        float a20 = 0.f, a21 = 0.f, a22 = 0.f, a23 = 0.f;
        float a30 = 0.f, a31 = 0.f, a32 = 0.f, a33 = 0.f;
        const int kbase = kq * 32;
        #pragma unroll 8
        for (int kk = 0; kk < 32; kk++) {
            const int k = kbase + kk;
            const float4 wv = *(const float4*)&ws_[k * 128 + ((ox ^ (k & 31)) << 2)];
            const float4 xv = *(const float4*)&xsrc[k * 12 + pg * 4];   // broadcast
            a00 = fmaf(wv.x, xv.x, a00); a01 = fmaf(wv.x, xv.y, a01);
            a02 = fmaf(wv.x, xv.z, a02); a03 = fmaf(wv.x, xv.w, a03);
            a10 = fmaf(wv.y, xv.x, a10); a11 = fmaf(wv.y, xv.y, a11);
            a12 = fmaf(wv.y, xv.z, a12); a13 = fmaf(wv.y, xv.w, a13);
            a20 = fmaf(wv.z, xv.x, a20); a21 = fmaf(wv.z, xv.y, a21);
            a22 = fmaf(wv.z, xv.z, a22); a23 = fmaf(wv.z, xv.w, a23);
            a30 = fmaf(wv.w, xv.x, a30); a31 = fmaf(wv.w, xv.y, a31);
            a32 = fmaf(wv.w, xv.z, a32); a33 = fmaf(wv.w, xv.w, a33);
        }
        *(float4*)&red[t * 20 +  0] = make_float4(a00, a01, a02, a03);
        *(float4*)&red[t * 20 +  4] = make_float4(a10, a11, a12, a13);
        *(float4*)&red[t * 20 +  8] = make_float4(a20, a21, a22, a23);
        *(float4*)&red[t * 20 + 12] = make_float4(a30, a31, a32, a33);
        __syncthreads();

        // --- combine 8 k-chunks: 1024 outputs, 2 per thread ---
        #pragma unroll
        for (int rr = 0; rr < 2; rr++) {
            const int fidx = rr * 512 + t;       // 0..1023
            const int hi   = fidx >> 4;          // pg*32 + ox  (0..63)
            const int lo   = fidx & 15;          // oi*4 + pi
            float s = red[(0 * 64 + hi) * 20 + lo]
                    + red[(1 * 64 + hi) * 20 + lo]
                    + red[(2 * 64 + hi) * 20 + lo]
                    + red[(3 * 64 + hi) * 20 + lo]
                    + red[(4 * 64 + hi) * 20 + lo]
                    + red[(5 * 64 + hi) * 20 + lo]
                    + red[(6 * 64 + hi) * 20 + lo]
                    + red[(7 * 64 + hi) * 20 + lo];
            const int o = (hi & 31) * 4 + (lo >> 2);    // 0..127
            const int p = (hi >> 5) * 4 + (lo & 3);     // 0..7
            if (phase == 0)      h1T[o * 12 + p]         = fmaxf(s, 0.f);
            else if (phase == 1) h1T[(128 + o) * 12 + p] = fmaxf(s, 0.f);
            else                 ys[p * 132 + o]         = s;
        }
        __syncthreads();
    }

    // --- LayerNorm: warp w (w<8) -> patch w.
    //     branch 0: normalize IN-PLACE into ys (e1 stays in smem).
    //     branch 1: write normalized e2 to g_emb.
    if ((t >> 5) < 8) {
        const int wid  = t >> 5;
        const int lane = t & 31;
        float* yr = ys + wid * 132;
        float v0 = yr[lane], v1 = yr[lane + 32], v2 = yr[lane + 64], v3 = yr[lane + 96];
        float s  = v0 + v1 + v2 + v3;
        float ss = v0 * v0 + v1 * v1 + v2 * v2 + v3 * v3;
        #pragma unroll
        for (int off = 16; off > 0; off >>= 1) {
            s  += __shfl_xor_sync(0xffffffffu, s,  off);
            ss += __shfl_xor_sync(0xffffffffu, ss, off);
        }
        const float mean = s * (1.f / 128.f);
        const float var  = ss * (1.f / 128.f) - mean * mean;
        const float rstd = rsqrtf(var + 1e-5f);
        const float* lg = branch ? g_dep  : g_img;
        const float* lb = branch ? be_dep : be_img;
        const float e0 = (v0 - mean) * rstd * lg[lane]      + lb[lane];
        const float e1 = (v1 - mean) * rstd * lg[lane + 32] + lb[lane + 32];
        const float e2 = (v2 - mean) * rstd * lg[lane + 64] + lb[lane + 64];
        const float e3 = (v3 - mean) * rstd * lg[lane + 96] + lb[lane + 96];
        if (branch) {
            float* outp = g_emb + (size_t)(p0 + wid) * 128;
            outp[lane]      = e0;
            outp[lane + 32] = e1;
            outp[lane + 64] = e2;
            outp[lane + 96] = e3;
        } else {
            yr[lane]      = e0;
            yr[lane + 32] = e1;
            yr[lane + 64] = e2;
            yr[lane + 96] = e3;
        }
    }
    __syncthreads();

    if (branch) {
        // --- producer: announce e2 completion, exit ---
        if (t == 0) {
            __threadfence();                 // release g_emb writes
            atomicAdd(&g_cnt1, 1u);
        }
        return;
    }

    // --- consumer: wait for all 50 branch-1 blocks of THIS launch ---
    if (t == 0) {
        unsigned ticket = atomicAdd(&g_cnt0, 1u) + 1u;     // my launch index
        unsigned target = ((ticket + 49u) / 50u) * 50u;    // 50 arrivals per launch
        while (true) {
            unsigned cur;
            asm volatile("ld.volatile.global.u32 %0, [%1];"
                         : "=r"(cur) : "l"(&g_cnt1) : "memory");
            if (cur >= target) break;
            __nanosleep(64);
        }
        __threadfence();                                   // acquire
    }
    __syncthreads();

    // --- logits for this block's 8 e1 rows (global patches p0..p0+7),
    //     two 4-row groups, each batch-uniform (4 divides 100).
    const float scale = expf(logit_scale[0]);
    #pragma unroll
    for (int grp = 0; grp < 2; grp++) {
        const int start = p0 + grp * 4;        // global e1 patch (0..796)
        const int b     = start / 100;
        const int n0    = start % 100;
        if (t < 100) {
            const float4* e2r = (const float4*)&g_emb[(size_t)(NPAT + b * 100 + t) * 128];
            const float* y0 = ys + (grp * 4 + 0) * 132;
            const float* y1 = ys + (grp * 4 + 1) * 132;
            const float* y2 = ys + (grp * 4 + 2) * 132;
            const float* y3 = ys + (grp * 4 + 3) * 132;
            float a0 = 0.f, a1 = 0.f, a2 = 0.f, a3 = 0.f;
            #pragma unroll 8
            for (int d4 = 0; d4 < 32; d4++) {
                const float4 c  = e2r[d4];
                const float4 e0 = *(const float4*)&y0[d4 * 4];
                const float4 e1 = *(const float4*)&y1[d4 * 4];
                const float4 e2 = *(const float4*)&y2[d4 * 4];
                const float4 e3 = *(const float4*)&y3[d4 * 4];
                a0 = fmaf(e0.x, c.x, a0); a0 = fmaf(e0.y, c.y, a0);
                a0 = fmaf(e0.z, c.z, a0); a0 = fmaf(e0.w, c.w, a0);
                a1 = fmaf(e1.x, c.x, a1); a1 = fmaf(e1.y, c.y, a1);
                a1 = fmaf(e1.z, c.z, a1); a1 = fmaf(e1.w, c.w, a1);
                a2 = fmaf(e2.x, c.x, a2); a2 = fmaf(e2.y, c.y, a2);
                a2 = fmaf(e2.z, c.z, a2); a2 = fmaf(e2.w, c.w, a2);
                a3 = fmaf(e3.x, c.x, a3); a3 = fmaf(e3.y, c.y, a3);
                a3 = fmaf(e3.z, c.z, a3); a3 = fmaf(e3.w, c.w, a3);
            }
            const float v0 = scale * a0;
            const float v1 = scale * a1;
            const float v2 = scale * a2;
            const float v3 = scale * a3;
            float* o1 = out + b * 10000;
            float* o2 = out + 40000 + b * 10000;
            o1[(n0 + 0) * 100 + t] = v0;
            o1[(n0 + 1) * 100 + t] = v1;
            o1[(n0 + 2) * 100 + t] = v2;
            o1[(n0 + 3) * 100 + t] = v3;
            o2[t * 100 + n0 + 0] = v0;
            o2[t * 100 + n0 + 1] = v1;
            o2[t * 100 + n0 + 2] = v2;
            o2[t * 100 + n0 + 3] = v3;
        }
    }
}

// ---------------------------------------------------------------------------
// Inputs: feat_c1, feat_c2, mask_c1, img_conv_w, img_conv_b, img_w1, img_w2,
// img_ln_g, img_ln_b, depth_conv_w, depth_conv_b, depth_w1, depth_w2,
// depth_ln_g, depth_ln_b, logit_scale
// ---------------------------------------------------------------------------
extern "C" void kernel_launch(void* const* d_in, const int* in_sizes, int n_in,
                              void* d_out, int out_size)
{
    cudaFuncSetAttribute(tail_kernel, cudaFuncAttributeMaxDynamicSharedMemorySize,
                         MLP_SMEM_BYTES);

    conv_kernel<<<800, 256>>>((const float*)d_in[0], (const float*)d_in[1],
                              (const float*)d_in[3],  (const float*)d_in[4],
                              (const float*)d_in[9],  (const float*)d_in[10]);

    tail_kernel<<<100, 512, MLP_SMEM_BYTES>>>(
                             (const float*)d_in[5],  (const float*)d_in[6],
                             (const float*)d_in[7],  (const float*)d_in[8],
                             (const float*)d_in[11], (const float*)d_in[12],
                             (const float*)d_in[13], (const float*)d_in[14],
                             (const float*)d_in[15], (float*)d_out);
}

// round 15
// speedup vs baseline: 1.0501x; 1.0501x over previous
#include <cuda_runtime.h>

// Fixed shapes: B=4, C=256, H=W=160, CPS=16 -> nv=nh=10, N=100, NPAT=400/branch
#define HH   160
#define WW   160
#define CC   256
#define NPAT 400
#define ENC  128

__device__ float g_conv_out[2 * NPAT * 256];   // [branch][patch][pix]
__device__ float g_emb[2 * NPAT * ENC];        // [branch][patch][enc]
__device__ unsigned g_cnt;                     // monotonic barrier ticket counter

// ---------------------------------------------------------------------------
// Kernel A: channel-reduce conv + bias + relu. K split 4 ways (measured best:
// 34.4us @ 78.5% DRAM). 800 blocks x 256 threads; block = 64 f4 outputs.
// ---------------------------------------------------------------------------
__global__ void __launch_bounds__(256) conv_kernel(
    const float* __restrict__ f1, const float* __restrict__ f2,
    const float* __restrict__ w_img, const float* __restrict__ b_img,
    const float* __restrict__ w_dep, const float* __restrict__ b_dep)
{
    __shared__ float  ws[256];
    __shared__ float4 part[4][64];
    __shared__ float  bias_s;

    const int t      = threadIdx.x;
    const int branch = blockIdx.x / 400;
    const int item0  = (blockIdx.x % 400) * 64;

    const float* wsrc = branch ? w_dep : w_img;
    ws[t] = wsrc[t];
    if (t == 0) bias_s = branch ? b_dep[0] : b_img[0];
    __syncthreads();

    const int kg = t >> 6;        // channel group 0..3
    const int ol = t & 63;
    const int r  = item0 + ol;    // 0..25599 (float4 items per branch)
    const int b  = r / 6400;      // 160*40 float4 per image
    const int r2 = r % 6400;
    const int h  = r2 / 40;
    const int w0 = (r2 % 40) * 4;

    const float* feat  = branch ? f2 : f1;
    const float4* base = (const float4*)(feat + (size_t)b * CC * HH * WW + h * WW + w0)
                         + (size_t)kg * 64 * 6400;   // channel stride = 6400 f4

    float4 acc = make_float4(0.f, 0.f, 0.f, 0.f);
    #pragma unroll 16
    for (int c = 0; c < 64; c++) {
        float4 v = base[c * 6400];
        float wc = ws[kg * 64 + c];
        acc.x = fmaf(v.x, wc, acc.x);
        acc.y = fmaf(v.y, wc, acc.y);
        acc.z = fmaf(v.z, wc, acc.z);
        acc.w = fmaf(v.w, wc, acc.w);
    }
    part[kg][ol] = acc;
    __syncthreads();

    if (t < 64) {
        float4 p0 = part[0][t], p1 = part[1][t], p2 = part[2][t], p3 = part[3][t];
        const float bb = bias_s;
        float4 o4;
        o4.x = fmaxf(p0.x + p1.x + p2.x + p3.x + bb, 0.f);
        o4.y = fmaxf(p0.y + p1.y + p2.y + p3.y + bb, 0.f);
        o4.z = fmaxf(p0.z + p1.z + p2.z + p3.z + bb, 0.f);
        o4.w = fmaxf(p0.w + p1.w + p2.w + p3.w + bb, 0.f);

        const int rr  = item0 + t;
        const int bb2 = rr / 6400;
        const int rr2 = rr % 6400;
        const int hh  = rr2 / 40;
        const int ww0 = (rr2 % 40) * 4;
        const int p   = bb2 * 100 + (hh >> 4) * 10 + (ww0 >> 4);
        const int pix = (hh & 15) * 16 + (ww0 & 15);
        *(float4*)&g_conv_out[(size_t)branch * NPAT * 256 + p * 256 + pix] = o4;
    }
}

// ---------------------------------------------------------------------------
// Kernel B: fused MLP + LayerNorm + grid-barrier + logits (R12 structure,
// 256 threads, PLUS weight-tile software pipelining: half of the next tile is
// LDG-prefetched into registers during the reduce step, hiding issue+latency).
// 100 blocks; smem 180KB -> 1 block/SM -> all blocks co-resident (barrier ok).
// smem floats: ws 32768 | asT 3072 | h1T 3072 | red 5120 | ys 1056
// ---------------------------------------------------------------------------
#define MLP_SMEM_FLOATS (32768 + 3072 + 3072 + 5120 + 1056)
#define MLP_SMEM_BYTES  (MLP_SMEM_FLOATS * 4)

__global__ void __launch_bounds__(256) tail_kernel(
    const float* __restrict__ w1_img, const float* __restrict__ w2_img,
    const float* __restrict__ g_img,  const float* __restrict__ be_img,
    const float* __restrict__ w1_dep, const float* __restrict__ w2_dep,
    const float* __restrict__ g_dep,  const float* __restrict__ be_dep,
    const float* __restrict__ logit_scale, float* __restrict__ out)
{
    extern __shared__ float sm[];
    float* ws_ = sm;                       // [256][128] swizzled weight tile
    float* asT = sm + 32768;               // [256][12]  x transposed
    float* h1T = sm + 32768 + 3072;        // [256][12]  h1 transposed
    float* red = sm + 32768 + 6144;        // [256][20]; reused as e1s in phase L
    float* ys  = sm + 32768 + 6144 + 5120; // [8][132]

    const int t      = threadIdx.x;
    const int branch = blockIdx.x / 50;
    const int p0     = blockIdx.x * 8;     // global patch base (0..792)

    const float* w1 = branch ? w1_dep : w1_img;
    const float* w2 = branch ? w2_dep : w2_img;

    // --- load asT[k][p] from g_conv_out (8 patches x 256) ---
    #pragma unroll
    for (int j = 0; j < 2; j++) {
        const int idx4 = j * 256 + t;      // 0..511
        const int p    = idx4 >> 6;        // 0..7
        const int k4   = idx4 & 63;
        float4 v = *(const float4*)&g_conv_out[(size_t)(p0 + p) * 256 + k4 * 4];
        asT[(k4 * 4 + 0) * 12 + p] = v.x;
        asT[(k4 * 4 + 1) * 12 + p] = v.y;
        asT[(k4 * 4 + 2) * 12 + p] = v.z;
        asT[(k4 * 4 + 3) * 12 + p] = v.w;
    }

    const int ox = t & 31;         // 4 outputs  ox*4..ox*4+3
    const int pg = (t >> 5) & 1;   // patches pg*4..pg*4+3
    const int kq = t >> 6;         // 64-k quarter
    const int lk4 = t & 63;        // loader: k4
    const int log = t >> 6;        // loader: o-group (0..3)

    // --- load tile 0 (W1 low half) in full ---
    {
        #pragma unroll
        for (int j = 0; j < 8; j++) {
            const int ob = log * 32 + j * 4;
            const int o4 = log * 8 + j;
            float4 v0 = *(const float4*)&w1[(size_t)(ob + 0) * 256 + lk4 * 4];
            float4 v1 = *(const float4*)&w1[(size_t)(ob + 1) * 256 + lk4 * 4];
            float4 v2 = *(const float4*)&w1[(size_t)(ob + 2) * 256 + lk4 * 4];
            float4 v3 = *(const float4*)&w1[(size_t)(ob + 3) * 256 + lk4 * 4];
            float4 t0 = make_float4(v0.x, v1.x, v2.x, v3.x);
            float4 t1 = make_float4(v0.y, v1.y, v2.y, v3.y);
            float4 t2 = make_float4(v0.z, v1.z, v2.z, v3.z);
            float4 t3 = make_float4(v0.w, v1.w, v2.w, v3.w);
            const int kb = lk4 * 4;
            *(float4*)&ws_[(kb + 0) * 128 + ((o4 ^ ((kb + 0) & 31)) << 2)] = t0;
            *(float4*)&ws_[(kb + 1) * 128 + ((o4 ^ ((kb + 1) & 31)) << 2)] = t1;
            *(float4*)&ws_[(kb + 2) * 128 + ((o4 ^ ((kb + 2) & 31)) << 2)] = t2;
            *(float4*)&ws_[(kb + 3) * 128 + ((o4 ^ ((kb + 3) & 31)) << 2)] = t3;
        }
    }
    __syncthreads();

    #pragma unroll 1
    for (int phase = 0; phase < 3; phase++) {
        // --- compute: 4 outs x 4 patches over this thread's 64-k quarter ---
        const float* xsrc = (phase < 2) ? asT : h1T;
        float a00 = 0.f, a01 = 0.f, a02 = 0.f, a03 = 0.f;
        float a10 = 0.f, a11 = 0.f, a12 = 0.f, a13 = 0.f;
        float a20 = 0.f, a21 = 0.f, a22 = 0.f, a23 = 0.f;
        float a30 = 0.f, a31 = 0.f, a32 = 0.f, a33 = 0.f;
        const int kbase = kq * 64;
        #pragma unroll 8
        for (int kk = 0; kk < 64; kk++) {
            const int k = kbase + kk;
            const float4 wv = *(const float4*)&ws_[k * 128 + ((ox ^ (k & 31)) << 2)];
            const float4 xv = *(const float4*)&xsrc[k * 12 + pg * 4];   // broadcast
            a00 = fmaf(wv.x, xv.x, a00); a01 = fmaf(wv.x, xv.y, a01);
            a02 = fmaf(wv.x, xv.z, a02); a03 = fmaf(wv.x, xv.w, a03);
            a10 = fmaf(wv.y, xv.x, a10); a11 = fmaf(wv.y, xv.y, a11);
            a12 = fmaf(wv.y, xv.z, a12); a13 = fmaf(wv.y, xv.w, a13);
            a20 = fmaf(wv.z, xv.x, a20); a21 = fmaf(wv.z, xv.y, a21);
            a22 = fmaf(wv.z, xv.z, a22); a23 = fmaf(wv.z, xv.w, a23);
            a30 = fmaf(wv.w, xv.x, a30); a31 = fmaf(wv.w, xv.y, a31);
            a32 = fmaf(wv.w, xv.z, a32); a33 = fmaf(wv.w, xv.w, a33);
        }
        *(float4*)&red[t * 20 +  0] = make_float4(a00, a01, a02, a03);
        *(float4*)&red[t * 20 +  4] = make_float4(a10, a11, a12, a13);
        *(float4*)&red[t * 20 +  8] = make_float4(a20, a21, a22, a23);
        *(float4*)&red[t * 20 + 12] = make_float4(a30, a31, a32, a33);
        __syncthreads();   // all ws_ reads of this phase complete after this

        // --- prefetch first half (j=0..3) of next tile into registers ---
        float4 pf[16];
        const float* nsrc = (phase == 0) ? (w1 + 128 * 256) : w2;
        if (phase < 2) {
            #pragma unroll
            for (int j = 0; j < 4; j++) {
                const int ob = log * 32 + j * 4;
                pf[j * 4 + 0] = *(const float4*)&nsrc[(size_t)(ob + 0) * 256 + lk4 * 4];
                pf[j * 4 + 1] = *(const float4*)&nsrc[(size_t)(ob + 1) * 256 + lk4 * 4];
                pf[j * 4 + 2] = *(const float4*)&nsrc[(size_t)(ob + 2) * 256 + lk4 * 4];
                pf[j * 4 + 3] = *(const float4*)&nsrc[(size_t)(ob + 3) * 256 + lk4 * 4];
            }
        }

        // --- combine k-quarters: 1024 outputs, 4 per thread (overlaps pf LDG) ---
        #pragma unroll
        for (int rr = 0; rr < 4; rr++) {
            const int fidx = rr * 256 + t;       // 0..1023
            const int hi   = fidx >> 4;          // pg*32 + ox  (0..63)
            const int lo   = fidx & 15;          // oi*4 + pi
            float s = red[(0 * 64 + hi) * 20 + lo]
                    + red[(1 * 64 + hi) * 20 + lo]
                    + red[(2 * 64 + hi) * 20 + lo]
                    + red[(3 * 64 + hi) * 20 + lo];
            const int o = (hi & 31) * 4 + (lo >> 2);    // 0..127
            const int p = (hi >> 5) * 4 + (lo & 3);     // 0..7
            if (phase == 0)      h1T[o * 12 + p]         = fmaxf(s, 0.f);
            else if (phase == 1) h1T[(128 + o) * 12 + p] = fmaxf(s, 0.f);
            else                 ys[p * 132 + o]         = s;
        }

        // --- store prefetched half + load remaining half (j=4..7) ---
        if (phase < 2) {
            #pragma unroll
            for (int j = 0; j < 4; j++) {
                const int o4 = log * 8 + j;
                float4 v0 = pf[j * 4 + 0], v1 = pf[j * 4 + 1];
                float4 v2 = pf[j * 4 + 2], v3 = pf[j * 4 + 3];
                float4 t0 = make_float4(v0.x, v1.x, v2.x, v3.x);
                float4 t1 = make_float4(v0.y, v1.y, v2.y, v3.y);
                float4 t2 = make_float4(v0.z, v1.z, v2.z, v3.z);
                float4 t3 = make_float4(v0.w, v1.w, v2.w, v3.w);
                const int kb = lk4 * 4;
                *(float4*)&ws_[(kb + 0) * 128 + ((o4 ^ ((kb + 0) & 31)) << 2)] = t0;
                *(float4*)&ws_[(kb + 1) * 128 + ((o4 ^ ((kb + 1) & 31)) << 2)] = t1;
                *(float4*)&ws_[(kb + 2) * 128 + ((o4 ^ ((kb + 2) & 31)) << 2)] = t2;
                *(float4*)&ws_[(kb + 3) * 128 + ((o4 ^ ((kb + 3) & 31)) << 2)] = t3;
            }
            #pragma unroll
            for (int j = 4; j < 8; j++) {
                const int ob = log * 32 + j * 4;
                const int o4 = log * 8 + j;
                float4 v0 = *(const float4*)&nsrc[(size_t)(ob + 0) * 256 + lk4 * 4];
                float4 v1 = *(const float4*)&nsrc[(size_t)(ob + 1) * 256 + lk4 * 4];
                float4 v2 = *(const float4*)&nsrc[(size_t)(ob + 2) * 256 + lk4 * 4];
                float4 v3 = *(const float4*)&nsrc[(size_t)(ob + 3) * 256 + lk4 * 4];
                float4 t0 = make_float4(v0.x, v1.x, v2.x, v3.x);
                float4 t1 = make_float4(v0.y, v1.y, v2.y, v3.y);
                float4 t2 = make_float4(v0.z, v1.z, v2.z, v3.z);
                float4 t3 = make_float4(v0.w, v1.w, v2.w, v3.w);
                const int kb = lk4 * 4;
                *(float4*)&ws_[(kb + 0) * 128 + ((o4 ^ ((kb + 0) & 31)) << 2)] = t0;
                *(float4*)&ws_[(kb + 1) * 128 + ((o4 ^ ((kb + 1) & 31)) << 2)] = t1;
                *(float4*)&ws_[(kb + 2) * 128 + ((o4 ^ ((kb + 2) & 31)) << 2)] = t2;
                *(float4*)&ws_[(kb + 3) * 128 + ((o4 ^ ((kb + 3) & 31)) << 2)] = t3;
            }
        }
        __syncthreads();
    }

    // --- LayerNorm: warp w -> patch w ---
    {
        const int wid  = t >> 5;
        const int lane = t & 31;
        const float* yr = ys + wid * 132;
        float v0 = yr[lane], v1 = yr[lane + 32], v2 = yr[lane + 64], v3 = yr[lane + 96];
        float s  = v0 + v1 + v2 + v3;
        float ss = v0 * v0 + v1 * v1 + v2 * v2 + v3 * v3;
        #pragma unroll
        for (int off = 16; off > 0; off >>= 1) {
            s  += __shfl_xor_sync(0xffffffffu, s,  off);
            ss += __shfl_xor_sync(0xffffffffu, ss, off);
        }
        const float mean = s * (1.f / 128.f);
        const float var  = ss * (1.f / 128.f) - mean * mean;
        const float rstd = rsqrtf(var + 1e-5f);
        const float* lg = branch ? g_dep  : g_img;
        const float* lb = branch ? be_dep : be_img;
        float* outp = g_emb + (size_t)(p0 + wid) * 128;
        outp[lane]      = (v0 - mean) * rstd * lg[lane]      + lb[lane];
        outp[lane + 32] = (v1 - mean) * rstd * lg[lane + 32] + lb[lane + 32];
        outp[lane + 64] = (v2 - mean) * rstd * lg[lane + 64] + lb[lane + 64];
        outp[lane + 96] = (v3 - mean) * rstd * lg[lane + 96] + lb[lane + 96];
    }
    __syncthreads();

    // --- grid barrier (monotonic tickets; all 100 blocks co-resident) ---
    if (t == 0) {
        __threadfence();                                   // release g_emb writes
        unsigned ticket = atomicAdd(&g_cnt, 1u) + 1u;
        unsigned target = ((ticket + 99u) / 100u) * 100u;  // end of this launch's batch
        while (true) {
            unsigned cur;
            asm volatile("ld.volatile.global.u32 %0, [%1];"
                         : "=r"(cur) : "l"(&g_cnt) : "memory");
            if (cur >= target) break;
            __nanosleep(64);
        }
        __threadfence();                                   // acquire
    }
    __syncthreads();

    // --- Phase L: logits (measured-best form). Block i -> b=i/25, n0=(i%25)*4.
    {
        float (*e1s)[128] = (float(*)[128])red;   // reuse red as e1s[4][128]
        const int b  = blockIdx.x / 25;
        const int n0 = (blockIdx.x % 25) * 4;

        if (t < 128) {
            const int r  = t >> 5;
            const int c4 = t & 31;
            *(float4*)&e1s[r][c4 * 4] =
                *(const float4*)&g_emb[(size_t)(b * 100 + n0 + r) * 128 + c4 * 4];
        }
        __syncthreads();

        if (t < 100) {
            const float scale = expf(logit_scale[0]);
            const float4* e2r = (const float4*)&g_emb[(size_t)(NPAT + b * 100 + t) * 128];
            float a0 = 0.f, a1 = 0.f, a2 = 0.f, a3 = 0.f;
            #pragma unroll 8
            for (int d4 = 0; d4 < 32; d4++) {
                const float4 c  = e2r[d4];
                const float4 e0 = *(const float4*)&e1s[0][d4 * 4];
                const float4 e1 = *(const float4*)&e1s[1][d4 * 4];
                const float4 e2 = *(const float4*)&e1s[2][d4 * 4];
                const float4 e3 = *(const float4*)&e1s[3][d4 * 4];
                a0 = fmaf(e0.x, c.x, a0); a0 = fmaf(e0.y, c.y, a0);
                a0 = fmaf(e0.z, c.z, a0); a0 = fmaf(e0.w, c.w, a0);
                a1 = fmaf(e1.x, c.x, a1); a1 = fmaf(e1.y, c.y, a1);
                a1 = fmaf(e1.z, c.z, a1); a1 = fmaf(e1.w, c.w, a1);
                a2 = fmaf(e2.x, c.x, a2); a2 = fmaf(e2.y, c.y, a2);
                a2 = fmaf(e2.z, c.z, a2); a2 = fmaf(e2.w, c.w, a2);
                a3 = fmaf(e3.x, c.x, a3); a3 = fmaf(e3.y, c.y, a3);
                a3 = fmaf(e3.z, c.z, a3); a3 = fmaf(e3.w, c.w, a3);
            }
            const float v0 = scale * a0;
            const float v1 = scale * a1;
            const float v2 = scale * a2;
            const float v3 = scale * a3;
            float* o1 = out + b * 10000;
            float* o2 = out + 40000 + b * 10000;
            o1[(n0 + 0) * 100 + t] = v0;
            o1[(n0 + 1) * 100 + t] = v1;
            o1[(n0 + 2) * 100 + t] = v2;
            o1[(n0 + 3) * 100 + t] = v3;
            o2[t * 100 + n0 + 0] = v0;
            o2[t * 100 + n0 + 1] = v1;
            o2[t * 100 + n0 + 2] = v2;
            o2[t * 100 + n0 + 3] = v3;
        }
    }
}

// ---------------------------------------------------------------------------
// Inputs: feat_c1, feat_c2, mask_c1, img_conv_w, img_conv_b, img_w1, img_w2,
// img_ln_g, img_ln_b, depth_conv_w, depth_conv_b, depth_w1, depth_w2,
// depth_ln_g, depth_ln_b, logit_scale
// ---------------------------------------------------------------------------
extern "C" void kernel_launch(void* const* d_in, const int* in_sizes, int n_in,
                              void* d_out, int out_size)
{
    cudaFuncSetAttribute(tail_kernel, cudaFuncAttributeMaxDynamicSharedMemorySize,
                         MLP_SMEM_BYTES);

    conv_kernel<<<800, 256>>>((const float*)d_in[0], (const float*)d_in[1],
                              (const float*)d_in[3],  (const float*)d_in[4],
                              (const float*)d_in[9],  (const float*)d_in[10]);

    tail_kernel<<<100, 256, MLP_SMEM_BYTES>>>(
                             (const float*)d_in[5],  (const float*)d_in[6],
                             (const float*)d_in[7],  (const float*)d_in[8],
                             (const float*)d_in[11], (const float*)d_in[12],
                             (const float*)d_in[13], (const float*)d_in[14],
                             (const float*)d_in[15], (float*)d_out);
}